// round 17
// baseline (speedup 1.0000x reference)
#include <cuda_runtime.h>
#include <cuda_bf16.h>

// FINAL — converged optimum (19.2 -> 18.59us over 15 rounds).
// Design: linear layer distributes over the concat:
//   score[e] = A[src[e]] + B[dst[e]] + bias  with per-node 2-wide projections.
// Phase 1 (node_proj, ~7.75us): streams x once (51.2MB, DRAM floor ~7.4us);
//   W staged in smem, 7-SHFL value-halving butterfly, one coalesced 128B
//   store/warp, balanced persistent grid (3 iters/warp).
// Phase 2 (edge, ~10.8us): 2x8B random gathers/edge from the L2-resident
//   table; L1tex/MSHR-bound floor (occupancy-invariant 38-88%; DSMEM 4x worse).
// PDL stitches the phases with zero gap.

#define N_NODES 100000
#define N_EDGES 625000
#define GRID1_BLOCKS 521   // 4168 warps -> exactly 3 iterations/warp (12500 groups)

// Combined per-node projection table: g_AB[n] = {a0+bias0, a1+bias1, b0, b1}
__device__ float4 g_AB[N_NODES];

__global__ __launch_bounds__(256) void node_proj_kernel(
    const float4* __restrict__ x,    // [N_NODES * 32] float4
    const float4* __restrict__ W,    // [2 * 64] float4
    const float*  __restrict__ bias) // [2]
{
    __shared__ float4 s_W[128];      // full W: 2KB
    if (threadIdx.x < 128) s_W[threadIdx.x] = W[threadIdx.x];
    __syncthreads();

    int lane = threadIdx.x & 31;
    int g = lane >> 3;        // group 0..3
    int w = lane & 7;         // lane-in-group 0..7
    int warp_global = blockIdx.x * 8 + (threadIdx.x >> 5);
    const int n_warps = GRID1_BLOCKS * 8;
    const int N_GROUPS = N_NODES / 8;   // 12500 exactly

    // Per-lane bias for the final scalar: comp = lane&3 -> {a0,a1,b0,b1}.
    int comp = lane & 3;
    float lane_bias = (comp == 0) ? __ldg(&bias[0])
                    : (comp == 1) ? __ldg(&bias[1]) : 0.f;

    float* outp = (float*)g_AB;

    for (int grp = warp_global; grp < N_GROUPS; grp += n_warps) {
        int nodeA = grp * 8 + 2 * g;     // adjacent pair
        int nodeB = nodeA + 1;

        const float4* xa = x + nodeA * 32;
        const float4* xb = x + nodeB * 32;
        float4 u0 = xa[w];
        float4 u1 = xa[w + 8];
        float4 u2 = xa[w + 16];
        float4 u3 = xa[w + 24];
        float4 v0 = xb[w];
        float4 v1 = xb[w + 8];
        float4 v2 = xb[w + 16];
        float4 v3 = xb[w + 24];

        // acc[0..3] = nodeA {a0,a1,b0,b1}; acc[4..7] = nodeB {a0,a1,b0,b1}
        float acc[8];
        #pragma unroll
        for (int i = 0; i < 8; i++) acc[i] = 0.f;

        #pragma unroll
        for (int j = 0; j < 4; j++) {
            float4 u = (j == 0) ? u0 : (j == 1) ? u1 : (j == 2) ? u2 : u3;
            float4 v = (j == 0) ? v0 : (j == 1) ? v1 : (j == 2) ? v2 : v3;
            int col = w + 8 * j;
            float4 wa0 = s_W[col];        // class0 src half
            float4 wb0 = s_W[32 + col];   // class0 dst half
            float4 wa1 = s_W[64 + col];   // class1 src half
            float4 wb1 = s_W[96 + col];   // class1 dst half

            acc[0] += u.x * wa0.x + u.y * wa0.y + u.z * wa0.z + u.w * wa0.w;
            acc[1] += u.x * wa1.x + u.y * wa1.y + u.z * wa1.z + u.w * wa1.w;
            acc[2] += u.x * wb0.x + u.y * wb0.y + u.z * wb0.z + u.w * wb0.w;
            acc[3] += u.x * wb1.x + u.y * wb1.y + u.z * wb1.z + u.w * wb1.w;
            acc[4] += v.x * wa0.x + v.y * wa0.y + v.z * wa0.z + v.w * wa0.w;
            acc[5] += v.x * wa1.x + v.y * wa1.y + v.z * wa1.z + v.w * wa1.w;
            acc[6] += v.x * wb0.x + v.y * wb0.y + v.z * wb0.z + v.w * wb0.w;
            acc[7] += v.x * wb1.x + v.y * wb1.y + v.z * wb1.z + v.w * wb1.w;
        }

        // Value-halving butterfly over the 8-lane group: 7 SHFL total.
        {
            bool low = (w & 4) == 0;
            #pragma unroll
            for (int i = 0; i < 4; i++) {
                float t = low ? acc[4 + i] : acc[i];
                float r = __shfl_xor_sync(0xFFFFFFFFu, t, 4);
                acc[i] = (low ? acc[i] : acc[4 + i]) + r;
            }
        }
        {
            bool low = (w & 2) == 0;
            #pragma unroll
            for (int i = 0; i < 2; i++) {
                float t = low ? acc[2 + i] : acc[i];
                float r = __shfl_xor_sync(0xFFFFFFFFu, t, 2);
                acc[i] = (low ? acc[i] : acc[2 + i]) + r;
            }
        }
        float res;
        {
            bool low = (w & 1) == 0;
            float t = low ? acc[1] : acc[0];
            float r = __shfl_xor_sync(0xFFFFFFFFu, t, 1);
            res = (low ? acc[0] : acc[1]) + r;
        }

        // One coalesced 128B store per warp: float index = grp*32 + lane.
        outp[grp * 32 + lane] = res + lane_bias;
    }

#if __CUDA_ARCH__ >= 900
    cudaTriggerProgrammaticLaunchCompletion();
#endif
}

// 1 edge per thread. PDL: index loads precede the grid-dependency-sync.
// Bias folded into the table at projection time.
__global__ __launch_bounds__(256) void edge_score_kernel(
    const int* __restrict__ ei,      // [2 * N_EDGES] int32
    float2* __restrict__ out)        // [N_EDGES] float2
{
    int e = blockIdx.x * blockDim.x + threadIdx.x;

    int s = 0, d = 0;
    bool valid = (e < N_EDGES);
    if (valid) {
        s = __ldg(&ei[e]);
        d = __ldg(&ei[N_EDGES + e]);
    }

#if __CUDA_ARCH__ >= 900
    cudaGridDependencySynchronize();
#endif

    if (!valid) return;

    const float2* AB = (const float2*)g_AB;  // A at 2*n, B at 2*n+1
    float2 A = AB[2 * s];
    float2 B = AB[2 * d + 1];

    out[e] = make_float2(A.x + B.x, A.y + B.y);
}

extern "C" void kernel_launch(void* const* d_in, const int* in_sizes, int n_in,
                              void* d_out, int out_size)
{
    const float4* x   = (const float4*)d_in[0];   // [100000, 128] f32
    const int*    ei  = (const int*)d_in[1];      // [2, 625000] i32
    const float4* W   = (const float4*)d_in[2];   // [2, 256] f32
    const float*  b   = (const float*)d_in[3];    // [2] f32
    float2*       out = (float2*)d_out;

    // Kernel 1: balanced persistent grid (exactly 3 iterations per warp).
    node_proj_kernel<<<GRID1_BLOCKS, 256>>>(x, W, b);

    // Kernel 2: per-edge gather with programmatic dependent launch.
    int grid2 = (N_EDGES + 255) / 256;

    cudaLaunchConfig_t cfg = {};
    cfg.gridDim  = dim3((unsigned)grid2, 1, 1);
    cfg.blockDim = dim3(256, 1, 1);
    cfg.dynamicSmemBytes = 0;
    cfg.stream = 0;
    cudaLaunchAttribute attrs[1];
    attrs[0].id = cudaLaunchAttributeProgrammaticStreamSerialization;
    attrs[0].val.programmaticStreamSerializationAllowed = 1;
    cfg.attrs = attrs;
    cfg.numAttrs = 1;

    cudaError_t err = cudaLaunchKernelEx(&cfg, edge_score_kernel, ei, out);
    if (err != cudaSuccess) {
        edge_score_kernel<<<grid2, 256>>>(ei, out);
    }
}